// round 2
// baseline (speedup 1.0000x reference)
#include <cuda_runtime.h>

#define CN0 50000
#define CN1 150000
#define CN2 20000
#define CN3 5000
#define CN4 1000
#define CE0 800000
#define CE1 1500000
#define CNNZ 300000
#define DD 64

// ---------------- scratch (static device globals; no allocation) ----------------
__device__ float g_m0[CN0 * DD];    // x0 @ W_hbs0
__device__ float g_m1[CN1 * DD];    // x1 @ W_hbs1
__device__ float g_ms[CN1 * DD];    // x1 @ W_hbns_s
__device__ float g_mt[CN0 * DD];    // x0 @ W_hbns_t
__device__ float g_accA0[CN0 * DD]; // segsum for x_0_to_0 (pre-relu)
__device__ float g_accB0[CN0 * DD]; // segsum for x_1_to_0 (pre-relu)
__device__ float g_accA1[CN1 * DD]; // segsum for x_1_to_1 (pre-relu)
__device__ float g_accB1[CN1 * DD]; // segsum for x_0_to_1 (pre-relu)
__device__ float g_coeff0[CE0];
__device__ float g_coeff1[CE1];

// ---------------- packed f32x2 helpers (Blackwell FFMA2) ----------------
__device__ __forceinline__ unsigned long long pack2(float x, float y) {
    unsigned long long r;
    asm("mov.b64 %0, {%1,%2};" : "=l"(r) : "f"(x), "f"(y));
    return r;
}
__device__ __forceinline__ void fma2(unsigned long long& d, unsigned long long a,
                                     unsigned long long b) {
    asm("fma.rn.f32x2 %0, %1, %2, %0;" : "+l"(d) : "l"(a), "l"(b));
}
__device__ __forceinline__ float2 unpack2(unsigned long long v) {
    float2 f;
    asm("mov.b64 {%0,%1}, %2;" : "=f"(f.x), "=f"(f.y) : "l"(v));
    return f;
}

// ---------------- per-edge coefficient: coeff = val * (cci . a) ----------------
__global__ void coeff_kernel(const float* __restrict__ val, const float* __restrict__ cci,
                             const float* __restrict__ a, float* __restrict__ coeff, int E) {
    int e = blockIdx.x * blockDim.x + threadIdx.x;
    if (e >= E) return;
    float c = cci[e * 3 + 0] * a[0] + cci[e * 3 + 1] * a[1] + cci[e * 3 + 2] * a[2];
    coeff[e] = val[e] * c;
}

// ---------------- GEMM: out[N,64] = X[N,64] @ W[64,64] ----------------
// Block = 256 threads, 32 rows/block. W + X tile in smem, packed f32x2 FMAs.
// Each thread: 4 rows x 2 cols (cols 2*c2, 2*c2+1).
__global__ __launch_bounds__(256) void gemm64(const float* __restrict__ X,
                                              const float* __restrict__ W,
                                              float* __restrict__ out, int N) {
    __shared__ __align__(16) float sW[64 * 64];
    __shared__ __align__(16) float sX[32 * 64];
    int tid = threadIdx.x;
#pragma unroll
    for (int i = 0; i < 16; i++) sW[tid + i * 256] = W[tid + i * 256];
    int r0 = blockIdx.x * 32;
#pragma unroll
    for (int i = 0; i < 8; i++) {
        int li = tid + i * 256;
        int gr = r0 + (li >> 6);
        sX[li] = (gr < N) ? X[(long)gr * 64 + (li & 63)] : 0.f;
    }
    __syncthreads();
    int c2 = tid & 31;
    int rb = (tid >> 5) * 4;
    unsigned long long a0 = 0, a1 = 0, a2 = 0, a3 = 0;
    const unsigned long long* sW2 = reinterpret_cast<const unsigned long long*>(sW);
    const float* xr = &sX[rb * 64];
#pragma unroll
    for (int k = 0; k < 64; k++) {
        unsigned long long w2 = sW2[k * 32 + c2];
        fma2(a0, pack2(xr[k], xr[k]), w2);
        fma2(a1, pack2(xr[64 + k], xr[64 + k]), w2);
        fma2(a2, pack2(xr[128 + k], xr[128 + k]), w2);
        fma2(a3, pack2(xr[192 + k], xr[192 + k]), w2);
    }
    float2* o2 = (float2*)out;
    unsigned long long accs[4] = {a0, a1, a2, a3};
#pragma unroll
    for (int i = 0; i < 4; i++) {
        int row = r0 + rb + i;
        if (row < N) o2[(long)row * 32 + c2] = unpack2(accs[i]);
    }
}

// ---------------- fused epilogue GEMM: out = relu((relu(A)+relu(B)) @ W) ----------------
__global__ __launch_bounds__(256) void gemm64_fused(const float* __restrict__ A,
                                                    const float* __restrict__ B,
                                                    const float* __restrict__ W,
                                                    float* __restrict__ out, int N) {
    __shared__ __align__(16) float sW[64 * 64];
    __shared__ __align__(16) float sX[32 * 64];
    int tid = threadIdx.x;
#pragma unroll
    for (int i = 0; i < 16; i++) sW[tid + i * 256] = W[tid + i * 256];
    int r0 = blockIdx.x * 32;
#pragma unroll
    for (int i = 0; i < 8; i++) {
        int li = tid + i * 256;
        int gr = r0 + (li >> 6);
        float v = 0.f;
        if (gr < N) {
            long idx = (long)gr * 64 + (li & 63);
            v = fmaxf(A[idx], 0.f) + fmaxf(B[idx], 0.f);
        }
        sX[li] = v;
    }
    __syncthreads();
    int c2 = tid & 31;
    int rb = (tid >> 5) * 4;
    unsigned long long a0 = 0, a1 = 0, a2 = 0, a3 = 0;
    const unsigned long long* sW2 = reinterpret_cast<const unsigned long long*>(sW);
    const float* xr = &sX[rb * 64];
#pragma unroll
    for (int k = 0; k < 64; k++) {
        unsigned long long w2 = sW2[k * 32 + c2];
        fma2(a0, pack2(xr[k], xr[k]), w2);
        fma2(a1, pack2(xr[64 + k], xr[64 + k]), w2);
        fma2(a2, pack2(xr[128 + k], xr[128 + k]), w2);
        fma2(a3, pack2(xr[192 + k], xr[192 + k]), w2);
    }
    float2* o2 = (float2*)out;
    unsigned long long accs[4] = {a0, a1, a2, a3};
#pragma unroll
    for (int i = 0; i < 4; i++) {
        int row = r0 + rb + i;
        if (row < N) {
            float2 v = unpack2(accs[i]);
            v.x = fmaxf(v.x, 0.f);
            v.y = fmaxf(v.y, 0.f);
            o2[(long)row * 32 + c2] = v;
        }
    }
}

// ---------------- adjacency scatter: acc[dst] += coeff * m[src], 16 thr/edge ----------------
__global__ __launch_bounds__(256) void scatter_edges(const float* __restrict__ m,
                                                     const float* __restrict__ coeff,
                                                     const int* __restrict__ src,
                                                     const int* __restrict__ dst,
                                                     float* __restrict__ acc, int E) {
    long t = (long)blockIdx.x * blockDim.x + threadIdx.x;
    int e = (int)(t >> 4);
    if (e >= E) return;
    int sub = (int)(t & 15);
    int s = src[e];
    int d = dst[e];
    float c = coeff[e];
    float4 v = reinterpret_cast<const float4*>(m + (long)s * 64)[sub];
    v.x *= c; v.y *= c; v.z *= c; v.w *= c;
    float* p = acc + (long)d * 64 + sub * 4;
    asm volatile("red.global.add.v4.f32 [%0], {%1,%2,%3,%4};"
                 :: "l"(p), "f"(v.x), "f"(v.y), "f"(v.z), "f"(v.w) : "memory");
}

// ---------------- incidence scatter (both directions in one pass) ----------------
__global__ __launch_bounds__(256) void scatter_inc(const float* __restrict__ ms,
                                                   const float* __restrict__ mt,
                                                   const int* __restrict__ row,
                                                   const int* __restrict__ col,
                                                   const float* __restrict__ val,
                                                   float* __restrict__ accB0,
                                                   float* __restrict__ accB1, int E) {
    long t = (long)blockIdx.x * blockDim.x + threadIdx.x;
    int e = (int)(t >> 4);
    if (e >= E) return;
    int sub = (int)(t & 15);
    int r = row[e];
    int c = col[e];
    float v = val[e];
    // x_1_to_0 : accB0[row] += v * ms[col]
    float4 a = reinterpret_cast<const float4*>(ms + (long)c * 64)[sub];
    a.x *= v; a.y *= v; a.z *= v; a.w *= v;
    float* p0 = accB0 + (long)r * 64 + sub * 4;
    asm volatile("red.global.add.v4.f32 [%0], {%1,%2,%3,%4};"
                 :: "l"(p0), "f"(a.x), "f"(a.y), "f"(a.z), "f"(a.w) : "memory");
    // x_0_to_1 : accB1[col] += v * mt[row]
    float4 b = reinterpret_cast<const float4*>(mt + (long)r * 64)[sub];
    b.x *= v; b.y *= v; b.z *= v; b.w *= v;
    float* p1 = accB1 + (long)c * 64 + sub * 4;
    asm volatile("red.global.add.v4.f32 [%0], {%1,%2,%3,%4};"
                 :: "l"(p1), "f"(b.x), "f"(b.y), "f"(b.z), "f"(b.w) : "memory");
}

// ---------------- launch ----------------
extern "C" void kernel_launch(void* const* d_in, const int* in_sizes, int n_in,
                              void* d_out, int out_size) {
    const float* x0   = (const float*)d_in[0];
    const float* x1   = (const float*)d_in[1];
    const float* x2   = (const float*)d_in[2];
    const float* x3   = (const float*)d_in[3];
    const float* x4   = (const float*)d_in[4];
    const int*   adj0 = (const int*)d_in[5];
    const float* adj0v= (const float*)d_in[6];
    const int*   adj1 = (const int*)d_in[7];
    const float* adj1v= (const float*)d_in[8];
    const int*   inc  = (const int*)d_in[9];
    const float* incv = (const float*)d_in[10];
    const float* cci0 = (const float*)d_in[11];
    const float* cci1 = (const float*)d_in[12];
    const float* Whbs0= (const float*)d_in[13];
    const float* ahbs0= (const float*)d_in[14];
    const float* Whbs1= (const float*)d_in[15];
    const float* ahbs1= (const float*)d_in[16];
    const float* Ws   = (const float*)d_in[17];
    const float* Wt   = (const float*)d_in[18];
    const float* Wag0 = (const float*)d_in[19];
    const float* Wag1 = (const float*)d_in[20];
    float* out = (float*)d_out;

    float *pm0, *pm1, *pms, *pmt, *pA0, *pB0, *pA1, *pB1, *pc0, *pc1;
    cudaGetSymbolAddress((void**)&pm0, g_m0);
    cudaGetSymbolAddress((void**)&pm1, g_m1);
    cudaGetSymbolAddress((void**)&pms, g_ms);
    cudaGetSymbolAddress((void**)&pmt, g_mt);
    cudaGetSymbolAddress((void**)&pA0, g_accA0);
    cudaGetSymbolAddress((void**)&pB0, g_accB0);
    cudaGetSymbolAddress((void**)&pA1, g_accA1);
    cudaGetSymbolAddress((void**)&pB1, g_accB1);
    cudaGetSymbolAddress((void**)&pc0, g_coeff0);
    cudaGetSymbolAddress((void**)&pc1, g_coeff1);

    // zero accumulators (graph-capturable memset nodes)
    cudaMemsetAsync(pA0, 0, sizeof(float) * (size_t)CN0 * DD);
    cudaMemsetAsync(pB0, 0, sizeof(float) * (size_t)CN0 * DD);
    cudaMemsetAsync(pA1, 0, sizeof(float) * (size_t)CN1 * DD);
    cudaMemsetAsync(pB1, 0, sizeof(float) * (size_t)CN1 * DD);

    // per-edge coefficients
    coeff_kernel<<<(CE0 + 255) / 256, 256>>>(adj0v, cci0, ahbs0, pc0, CE0);
    coeff_kernel<<<(CE1 + 255) / 256, 256>>>(adj1v, cci1, ahbs1, pc1, CE1);

    // dense projections
    gemm64<<<(CN0 + 31) / 32, 256>>>(x0, Whbs0, pm0, CN0);
    gemm64<<<(CN1 + 31) / 32, 256>>>(x1, Whbs1, pm1, CN1);
    gemm64<<<(CN1 + 31) / 32, 256>>>(x1, Ws, pms, CN1);
    gemm64<<<(CN0 + 31) / 32, 256>>>(x0, Wt, pmt, CN0);

    // sparse message passing (atomic segment sums)
    scatter_edges<<<(CE0 * 16 + 255) / 256, 256>>>(pm0, pc0, adj0, adj0 + CE0, pA0, CE0);
    scatter_edges<<<(CE1 * 16 + 255) / 256, 256>>>(pm1, pc1, adj1, adj1 + CE1, pA1, CE1);
    scatter_inc<<<(CNNZ * 16 + 255) / 256, 256>>>(pms, pmt, inc, inc + CNNZ, incv, pB0, pB1, CNNZ);

    // fused relu-add-GEMM-relu epilogues straight into d_out
    gemm64_fused<<<(CN0 + 31) / 32, 256>>>(pA0, pB0, Wag0, out, CN0);
    gemm64_fused<<<(CN1 + 31) / 32, 256>>>(pA1, pB1, Wag1, out + (long)CN0 * DD, CN1);

    // pass-through outputs
    cudaMemcpyAsync(out + (long)(CN0 + CN1) * DD, x2, sizeof(float) * (size_t)CN2 * DD,
                    cudaMemcpyDeviceToDevice);
    cudaMemcpyAsync(out + (long)(CN0 + CN1 + CN2) * DD, x3, sizeof(float) * (size_t)CN3 * DD,
                    cudaMemcpyDeviceToDevice);
    cudaMemcpyAsync(out + (long)(CN0 + CN1 + CN2 + CN3) * DD, x4, sizeof(float) * (size_t)CN4 * DD,
                    cudaMemcpyDeviceToDevice);
}

// round 4
// speedup vs baseline: 1.0864x; 1.0864x over previous
#include <cuda_runtime.h>

#define CN0 50000
#define CN1 150000
#define CN2 20000
#define CN3 5000
#define CN4 1000
#define CE0 800000
#define CE1 1500000
#define CNNZ 300000
#define DD 64

// ---------------- scratch (static device globals; no allocation) ----------------
__device__ float g_m0[CN0 * DD];    // x0 @ W_hbs0
__device__ float g_m1[CN1 * DD];    // x1 @ W_hbs1
__device__ float g_ms[CN1 * DD];    // x1 @ W_hbns_s
__device__ float g_mt[CN0 * DD];    // x0 @ W_hbns_t
__device__ float g_accA0[CN0 * DD];
__device__ float g_accB0[CN0 * DD];
__device__ float g_accA1[CN1 * DD];
__device__ float g_accB1[CN1 * DD];

// ---------------- packed f32x2 helpers (Blackwell FFMA2) ----------------
__device__ __forceinline__ unsigned long long pack2(float x, float y) {
    unsigned long long r;
    asm("mov.b64 %0, {%1,%2};" : "=l"(r) : "f"(x), "f"(y));
    return r;
}
__device__ __forceinline__ void fma2(unsigned long long& d, unsigned long long a,
                                     unsigned long long b) {
    asm("fma.rn.f32x2 %0, %1, %2, %0;" : "+l"(d) : "l"(a), "l"(b));
}
__device__ __forceinline__ float2 unpack2(unsigned long long v) {
    float2 f;
    asm("mov.b64 {%0,%1}, %2;" : "=f"(f.x), "=f"(f.y) : "l"(v));
    return f;
}

// =====================================================================
// Dual GEMM: out1 = X@W1, out2 = X@W2.  128 rows/block, 256 threads.
// Thread (tx=tid&15, ty=tid>>4): 8 rows (ty*8..+7) x 4 cols (tx*4..+3) per W.
// X stored transposed+swizzled in smem: elem(row,k) at float index
//   k*128 + ((rowgrp ^ (k&31))<<2) + (row&3),  rowgrp=row>>2  (conflict-free f4 loads)
// =====================================================================
__global__ __launch_bounds__(256) void gemm64_dual(const float* __restrict__ X,
                                                   const float* __restrict__ W1,
                                                   const float* __restrict__ W2,
                                                   float* __restrict__ out1,
                                                   float* __restrict__ out2, int N) {
    __shared__ __align__(16) float sW1[64 * 64];
    __shared__ __align__(16) float sW2[64 * 64];
    __shared__ __align__(16) float sXT[128 * 64];
    int tid = threadIdx.x;
#pragma unroll
    for (int i = 0; i < 16; i++) {
        sW1[tid + i * 256] = W1[tid + i * 256];
        sW2[tid + i * 256] = W2[tid + i * 256];
    }
    long r0 = (long)blockIdx.x * 128;
#pragma unroll
    for (int i = 0; i < 32; i++) {
        int li = tid + i * 256;
        int row = li >> 6, col = li & 63;
        long gr = r0 + row;
        float v = (gr < N) ? X[gr * 64 + col] : 0.f;
        sXT[col * 128 + (((row >> 2) ^ (col & 31)) << 2) + (row & 3)] = v;
    }
    __syncthreads();

    int tx = tid & 15, ty = tid >> 4;
    unsigned long long a1[8][2], a2[8][2];
#pragma unroll
    for (int r = 0; r < 8; r++) { a1[r][0] = a1[r][1] = a2[r][0] = a2[r][1] = 0ull; }

    const float4* sXT4 = (const float4*)sXT;
    const ulonglong2* sW1v = (const ulonglong2*)sW1;
    const ulonglong2* sW2v = (const ulonglong2*)sW2;
    int g0 = 2 * ty, g1 = 2 * ty + 1;
#pragma unroll 8
    for (int k = 0; k < 64; k++) {
        float4 xa = sXT4[k * 32 + (g0 ^ (k & 31))];
        float4 xb = sXT4[k * 32 + (g1 ^ (k & 31))];
        ulonglong2 w1 = sW1v[k * 16 + tx];
        ulonglong2 w2 = sW2v[k * 16 + tx];
        float xs[8] = {xa.x, xa.y, xa.z, xa.w, xb.x, xb.y, xb.z, xb.w};
#pragma unroll
        for (int r = 0; r < 8; r++) {
            unsigned long long xx = pack2(xs[r], xs[r]);
            fma2(a1[r][0], xx, w1.x); fma2(a1[r][1], xx, w1.y);
            fma2(a2[r][0], xx, w2.x); fma2(a2[r][1], xx, w2.y);
        }
    }
#pragma unroll
    for (int r = 0; r < 8; r++) {
        long row = r0 + ty * 8 + r;
        if (row < N) {
            float2 lo = unpack2(a1[r][0]), hi = unpack2(a1[r][1]);
            ((float4*)out1)[row * 16 + tx] = make_float4(lo.x, lo.y, hi.x, hi.y);
            lo = unpack2(a2[r][0]); hi = unpack2(a2[r][1]);
            ((float4*)out2)[row * 16 + tx] = make_float4(lo.x, lo.y, hi.x, hi.y);
        }
    }
}

// =====================================================================
// Fused epilogue: out = relu((relu(A)+relu(B)) @ W).  Same tiling, single W.
// =====================================================================
__global__ __launch_bounds__(256) void gemm64_fused(const float* __restrict__ A,
                                                    const float* __restrict__ B,
                                                    const float* __restrict__ W,
                                                    float* __restrict__ out, int N) {
    __shared__ __align__(16) float sW[64 * 64];
    __shared__ __align__(16) float sXT[128 * 64];
    int tid = threadIdx.x;
#pragma unroll
    for (int i = 0; i < 16; i++) sW[tid + i * 256] = W[tid + i * 256];
    long r0 = (long)blockIdx.x * 128;
#pragma unroll
    for (int i = 0; i < 32; i++) {
        int li = tid + i * 256;
        int row = li >> 6, col = li & 63;
        long gr = r0 + row;
        float v = 0.f;
        if (gr < N) {
            long idx = gr * 64 + col;
            v = fmaxf(A[idx], 0.f) + fmaxf(B[idx], 0.f);
        }
        sXT[col * 128 + (((row >> 2) ^ (col & 31)) << 2) + (row & 3)] = v;
    }
    __syncthreads();

    int tx = tid & 15, ty = tid >> 4;
    unsigned long long a1[8][2];
#pragma unroll
    for (int r = 0; r < 8; r++) { a1[r][0] = a1[r][1] = 0ull; }

    const float4* sXT4 = (const float4*)sXT;
    const ulonglong2* sWv = (const ulonglong2*)sW;
    int g0 = 2 * ty, g1 = 2 * ty + 1;
#pragma unroll 8
    for (int k = 0; k < 64; k++) {
        float4 xa = sXT4[k * 32 + (g0 ^ (k & 31))];
        float4 xb = sXT4[k * 32 + (g1 ^ (k & 31))];
        ulonglong2 w = sWv[k * 16 + tx];
        float xs[8] = {xa.x, xa.y, xa.z, xa.w, xb.x, xb.y, xb.z, xb.w};
#pragma unroll
        for (int r = 0; r < 8; r++) {
            unsigned long long xx = pack2(xs[r], xs[r]);
            fma2(a1[r][0], xx, w.x); fma2(a1[r][1], xx, w.y);
        }
    }
#pragma unroll
    for (int r = 0; r < 8; r++) {
        long row = r0 + ty * 8 + r;
        if (row < N) {
            float2 lo = unpack2(a1[r][0]), hi = unpack2(a1[r][1]);
            ((float4*)out)[row * 16 + tx] =
                make_float4(fmaxf(lo.x, 0.f), fmaxf(lo.y, 0.f),
                            fmaxf(hi.x, 0.f), fmaxf(hi.y, 0.f));
        }
    }
}

// ---------------- adjacency scatter with inline coeff ----------------
__global__ __launch_bounds__(256) void scatter_edges(const float* __restrict__ m,
                                                     const float* __restrict__ val,
                                                     const float* __restrict__ cci,
                                                     const float* __restrict__ a,
                                                     const int* __restrict__ src,
                                                     const int* __restrict__ dst,
                                                     float* __restrict__ acc, int E) {
    long t = (long)blockIdx.x * blockDim.x + threadIdx.x;
    int e = (int)(t >> 4);
    if (e >= E) return;
    int sub = (int)(t & 15);
    int s = src[e];
    int d = dst[e];
    float c = val[e] * (cci[e * 3 + 0] * a[0] + cci[e * 3 + 1] * a[1] + cci[e * 3 + 2] * a[2]);
    float4 v = reinterpret_cast<const float4*>(m + (long)s * 64)[sub];
    v.x *= c; v.y *= c; v.z *= c; v.w *= c;
    float* p = acc + (long)d * 64 + sub * 4;
    asm volatile("red.global.add.v4.f32 [%0], {%1,%2,%3,%4};"
                 :: "l"(p), "f"(v.x), "f"(v.y), "f"(v.z), "f"(v.w) : "memory");
}

// ---------------- incidence scatter (both directions) ----------------
__global__ __launch_bounds__(256) void scatter_inc(const float* __restrict__ ms,
                                                   const float* __restrict__ mt,
                                                   const int* __restrict__ row,
                                                   const int* __restrict__ col,
                                                   const float* __restrict__ val,
                                                   float* __restrict__ accB0,
                                                   float* __restrict__ accB1, int E) {
    long t = (long)blockIdx.x * blockDim.x + threadIdx.x;
    int e = (int)(t >> 4);
    if (e >= E) return;
    int sub = (int)(t & 15);
    int r = row[e];
    int c = col[e];
    float v = val[e];
    float4 a = reinterpret_cast<const float4*>(ms + (long)c * 64)[sub];
    a.x *= v; a.y *= v; a.z *= v; a.w *= v;
    float* p0 = accB0 + (long)r * 64 + sub * 4;
    asm volatile("red.global.add.v4.f32 [%0], {%1,%2,%3,%4};"
                 :: "l"(p0), "f"(a.x), "f"(a.y), "f"(a.z), "f"(a.w) : "memory");
    float4 b = reinterpret_cast<const float4*>(mt + (long)r * 64)[sub];
    b.x *= v; b.y *= v; b.z *= v; b.w *= v;
    float* p1 = accB1 + (long)c * 64 + sub * 4;
    asm volatile("red.global.add.v4.f32 [%0], {%1,%2,%3,%4};"
                 :: "l"(p1), "f"(b.x), "f"(b.y), "f"(b.z), "f"(b.w) : "memory");
}

// ---------------- launch ----------------
extern "C" void kernel_launch(void* const* d_in, const int* in_sizes, int n_in,
                              void* d_out, int out_size) {
    const float* x0   = (const float*)d_in[0];
    const float* x1   = (const float*)d_in[1];
    const float* x2   = (const float*)d_in[2];
    const float* x3   = (const float*)d_in[3];
    const float* x4   = (const float*)d_in[4];
    const int*   adj0 = (const int*)d_in[5];
    const float* adj0v= (const float*)d_in[6];
    const int*   adj1 = (const int*)d_in[7];
    const float* adj1v= (const float*)d_in[8];
    const int*   inc  = (const int*)d_in[9];
    const float* incv = (const float*)d_in[10];
    const float* cci0 = (const float*)d_in[11];
    const float* cci1 = (const float*)d_in[12];
    const float* Whbs0= (const float*)d_in[13];
    const float* ahbs0= (const float*)d_in[14];
    const float* Whbs1= (const float*)d_in[15];
    const float* ahbs1= (const float*)d_in[16];
    const float* Ws   = (const float*)d_in[17];
    const float* Wt   = (const float*)d_in[18];
    const float* Wag0 = (const float*)d_in[19];
    const float* Wag1 = (const float*)d_in[20];
    float* out = (float*)d_out;

    float *pm0, *pm1, *pms, *pmt, *pA0, *pB0, *pA1, *pB1;
    cudaGetSymbolAddress((void**)&pm0, g_m0);
    cudaGetSymbolAddress((void**)&pm1, g_m1);
    cudaGetSymbolAddress((void**)&pms, g_ms);
    cudaGetSymbolAddress((void**)&pmt, g_mt);
    cudaGetSymbolAddress((void**)&pA0, g_accA0);
    cudaGetSymbolAddress((void**)&pB0, g_accB0);
    cudaGetSymbolAddress((void**)&pA1, g_accA1);
    cudaGetSymbolAddress((void**)&pB1, g_accB1);

    // zero accumulators (graph-capturable memset nodes)
    cudaMemsetAsync(pA0, 0, sizeof(float) * (size_t)CN0 * DD);
    cudaMemsetAsync(pB0, 0, sizeof(float) * (size_t)CN0 * DD);
    cudaMemsetAsync(pA1, 0, sizeof(float) * (size_t)CN1 * DD);
    cudaMemsetAsync(pB1, 0, sizeof(float) * (size_t)CN1 * DD);

    // dense projections (dual-output: read X once, produce both projections)
    gemm64_dual<<<(CN0 + 127) / 128, 256>>>(x0, Whbs0, Wt, pm0, pmt, CN0);
    gemm64_dual<<<(CN1 + 127) / 128, 256>>>(x1, Whbs1, Ws, pm1, pms, CN1);

    // sparse message passing (atomic segment sums, coeff computed inline)
    scatter_edges<<<(CE0 * 16 + 255) / 256, 256>>>(pm0, adj0v, cci0, ahbs0,
                                                   adj0, adj0 + CE0, pA0, CE0);
    scatter_edges<<<(CE1 * 16 + 255) / 256, 256>>>(pm1, adj1v, cci1, ahbs1,
                                                   adj1, adj1 + CE1, pA1, CE1);
    scatter_inc<<<(CNNZ * 16 + 255) / 256, 256>>>(pms, pmt, inc, inc + CNNZ, incv, pB0, pB1, CNNZ);

    // fused relu-add-GEMM-relu epilogues straight into d_out
    gemm64_fused<<<(CN0 + 127) / 128, 256>>>(pA0, pB0, Wag0, out, CN0);
    gemm64_fused<<<(CN1 + 127) / 128, 256>>>(pA1, pB1, Wag1, out + (long)CN0 * DD, CN1);

    // pass-through outputs
    cudaMemcpyAsync(out + (long)(CN0 + CN1) * DD, x2, sizeof(float) * (size_t)CN2 * DD,
                    cudaMemcpyDeviceToDevice);
    cudaMemcpyAsync(out + (long)(CN0 + CN1 + CN2) * DD, x3, sizeof(float) * (size_t)CN3 * DD,
                    cudaMemcpyDeviceToDevice);
    cudaMemcpyAsync(out + (long)(CN0 + CN1 + CN2 + CN3) * DD, x4, sizeof(float) * (size_t)CN4 * DD,
                    cudaMemcpyDeviceToDevice);
}

// round 7
// speedup vs baseline: 1.1945x; 1.0995x over previous
#include <cuda_runtime.h>

#define CN0 50000
#define CN1 150000
#define CN2 20000
#define CN3 5000
#define CN4 1000
#define CE0 800000
#define CE1 1500000
#define CNNZ 300000
#define DD 64

// ---------------- scratch (static device globals; no allocation) ----------------
__device__ float g_m0[CN0 * DD];    // x0 @ W_hbs0
__device__ float g_m1[CN1 * DD];    // x1 @ W_hbs1
__device__ float g_ms[CN1 * DD];    // x1 @ W_hbns_s
__device__ float g_mt[CN0 * DD];    // x0 @ W_hbns_t
__device__ float g_accA0[CN0 * DD];
__device__ float g_accB0[CN0 * DD];
__device__ float g_accA1[CN1 * DD];
__device__ float g_accB1[CN1 * DD];

// ---------------- packed f32x2 helpers (Blackwell FFMA2) ----------------
__device__ __forceinline__ unsigned long long pack2(float x, float y) {
    unsigned long long r;
    asm("mov.b64 %0, {%1,%2};" : "=l"(r) : "f"(x), "f"(y));
    return r;
}
__device__ __forceinline__ void fma2(unsigned long long& d, unsigned long long a,
                                     unsigned long long b) {
    asm("fma.rn.f32x2 %0, %1, %2, %0;" : "+l"(d) : "l"(a), "l"(b));
}
__device__ __forceinline__ float2 unpack2(unsigned long long v) {
    float2 f;
    asm("mov.b64 {%0,%1}, %2;" : "=f"(f.x), "=f"(f.y) : "l"(v));
    return f;
}

// =====================================================================
// Dual GEMM: out1 = X@W1, out2 = X@W2.  128 rows/block, 256 threads.
// =====================================================================
__global__ __launch_bounds__(256) void gemm64_dual(const float* __restrict__ X,
                                                   const float* __restrict__ W1,
                                                   const float* __restrict__ W2,
                                                   float* __restrict__ out1,
                                                   float* __restrict__ out2, int N) {
    __shared__ __align__(16) float sW1[64 * 64];
    __shared__ __align__(16) float sW2[64 * 64];
    __shared__ __align__(16) float sXT[128 * 64];
    int tid = threadIdx.x;
#pragma unroll
    for (int i = 0; i < 16; i++) {
        sW1[tid + i * 256] = W1[tid + i * 256];
        sW2[tid + i * 256] = W2[tid + i * 256];
    }
    long r0 = (long)blockIdx.x * 128;
#pragma unroll
    for (int i = 0; i < 32; i++) {
        int li = tid + i * 256;
        int row = li >> 6, col = li & 63;
        long gr = r0 + row;
        float v = (gr < N) ? X[gr * 64 + col] : 0.f;
        sXT[col * 128 + (((row >> 2) ^ (col & 31)) << 2) + (row & 3)] = v;
    }
    __syncthreads();

    int tx = tid & 15, ty = tid >> 4;
    unsigned long long a1[8][2], a2[8][2];
#pragma unroll
    for (int r = 0; r < 8; r++) { a1[r][0] = a1[r][1] = a2[r][0] = a2[r][1] = 0ull; }

    const float4* sXT4 = (const float4*)sXT;
    const ulonglong2* sW1v = (const ulonglong2*)sW1;
    const ulonglong2* sW2v = (const ulonglong2*)sW2;
    int g0 = 2 * ty, g1 = 2 * ty + 1;
#pragma unroll 8
    for (int k = 0; k < 64; k++) {
        float4 xa = sXT4[k * 32 + (g0 ^ (k & 31))];
        float4 xb = sXT4[k * 32 + (g1 ^ (k & 31))];
        ulonglong2 w1 = sW1v[k * 16 + tx];
        ulonglong2 w2 = sW2v[k * 16 + tx];
        float xs[8] = {xa.x, xa.y, xa.z, xa.w, xb.x, xb.y, xb.z, xb.w};
#pragma unroll
        for (int r = 0; r < 8; r++) {
            unsigned long long xx = pack2(xs[r], xs[r]);
            fma2(a1[r][0], xx, w1.x); fma2(a1[r][1], xx, w1.y);
            fma2(a2[r][0], xx, w2.x); fma2(a2[r][1], xx, w2.y);
        }
    }
#pragma unroll
    for (int r = 0; r < 8; r++) {
        long row = r0 + ty * 8 + r;
        if (row < N) {
            float2 lo = unpack2(a1[r][0]), hi = unpack2(a1[r][1]);
            ((float4*)out1)[row * 16 + tx] = make_float4(lo.x, lo.y, hi.x, hi.y);
            lo = unpack2(a2[r][0]); hi = unpack2(a2[r][1]);
            ((float4*)out2)[row * 16 + tx] = make_float4(lo.x, lo.y, hi.x, hi.y);
        }
    }
}

// =====================================================================
// Fused epilogue: out = relu((relu(A)+relu(B)) @ W)
// =====================================================================
__global__ __launch_bounds__(256) void gemm64_fused(const float* __restrict__ A,
                                                    const float* __restrict__ B,
                                                    const float* __restrict__ W,
                                                    float* __restrict__ out, int N) {
    __shared__ __align__(16) float sW[64 * 64];
    __shared__ __align__(16) float sXT[128 * 64];
    int tid = threadIdx.x;
#pragma unroll
    for (int i = 0; i < 16; i++) sW[tid + i * 256] = W[tid + i * 256];
    long r0 = (long)blockIdx.x * 128;
#pragma unroll
    for (int i = 0; i < 32; i++) {
        int li = tid + i * 256;
        int row = li >> 6, col = li & 63;
        long gr = r0 + row;
        float v = 0.f;
        if (gr < N) {
            long idx = gr * 64 + col;
            v = fmaxf(A[idx], 0.f) + fmaxf(B[idx], 0.f);
        }
        sXT[col * 128 + (((row >> 2) ^ (col & 31)) << 2) + (row & 3)] = v;
    }
    __syncthreads();

    int tx = tid & 15, ty = tid >> 4;
    unsigned long long a1[8][2];
#pragma unroll
    for (int r = 0; r < 8; r++) { a1[r][0] = a1[r][1] = 0ull; }

    const float4* sXT4 = (const float4*)sXT;
    const ulonglong2* sWv = (const ulonglong2*)sW;
    int g0 = 2 * ty, g1 = 2 * ty + 1;
#pragma unroll 8
    for (int k = 0; k < 64; k++) {
        float4 xa = sXT4[k * 32 + (g0 ^ (k & 31))];
        float4 xb = sXT4[k * 32 + (g1 ^ (k & 31))];
        ulonglong2 w = sWv[k * 16 + tx];
        float xs[8] = {xa.x, xa.y, xa.z, xa.w, xb.x, xb.y, xb.z, xb.w};
#pragma unroll
        for (int r = 0; r < 8; r++) {
            unsigned long long xx = pack2(xs[r], xs[r]);
            fma2(a1[r][0], xx, w.x); fma2(a1[r][1], xx, w.y);
        }
    }
#pragma unroll
    for (int r = 0; r < 8; r++) {
        long row = r0 + ty * 8 + r;
        if (row < N) {
            float2 lo = unpack2(a1[r][0]), hi = unpack2(a1[r][1]);
            ((float4*)out)[row * 16 + tx] =
                make_float4(fmaxf(lo.x, 0.f), fmaxf(lo.y, 0.f),
                            fmaxf(hi.x, 0.f), fmaxf(hi.y, 0.f));
        }
    }
}

// ---------------- adjacency scatter with inline coeff ----------------
__global__ __launch_bounds__(256) void scatter_edges(const float* __restrict__ m,
                                                     const float* __restrict__ val,
                                                     const float* __restrict__ cci,
                                                     const float* __restrict__ a,
                                                     const int* __restrict__ src,
                                                     const int* __restrict__ dst,
                                                     float* __restrict__ acc, int E) {
    long t = (long)blockIdx.x * blockDim.x + threadIdx.x;
    int e = (int)(t >> 4);
    if (e >= E) return;
    int sub = (int)(t & 15);
    int s = src[e];
    int d = dst[e];
    float c = val[e] * (cci[e * 3 + 0] * a[0] + cci[e * 3 + 1] * a[1] + cci[e * 3 + 2] * a[2]);
    float4 v = reinterpret_cast<const float4*>(m + (long)s * 64)[sub];
    v.x *= c; v.y *= c; v.z *= c; v.w *= c;
    float* p = acc + (long)d * 64 + sub * 4;
    asm volatile("red.global.add.v4.f32 [%0], {%1,%2,%3,%4};"
                 :: "l"(p), "f"(v.x), "f"(v.y), "f"(v.z), "f"(v.w) : "memory");
}

// ---------------- incidence scatter (both directions) ----------------
__global__ __launch_bounds__(256) void scatter_inc(const float* __restrict__ ms,
                                                   const float* __restrict__ mt,
                                                   const int* __restrict__ row,
                                                   const int* __restrict__ col,
                                                   const float* __restrict__ val,
                                                   float* __restrict__ accB0,
                                                   float* __restrict__ accB1, int E) {
    long t = (long)blockIdx.x * blockDim.x + threadIdx.x;
    int e = (int)(t >> 4);
    if (e >= E) return;
    int sub = (int)(t & 15);
    int r = row[e];
    int c = col[e];
    float v = val[e];
    float4 a = reinterpret_cast<const float4*>(ms + (long)c * 64)[sub];
    a.x *= v; a.y *= v; a.z *= v; a.w *= v;
    float* p0 = accB0 + (long)r * 64 + sub * 4;
    asm volatile("red.global.add.v4.f32 [%0], {%1,%2,%3,%4};"
                 :: "l"(p0), "f"(a.x), "f"(a.y), "f"(a.z), "f"(a.w) : "memory");
    float4 b = reinterpret_cast<const float4*>(mt + (long)r * 64)[sub];
    b.x *= v; b.y *= v; b.z *= v; b.w *= v;
    float* p1 = accB1 + (long)c * 64 + sub * 4;
    asm volatile("red.global.add.v4.f32 [%0], {%1,%2,%3,%4};"
                 :: "l"(p1), "f"(b.x), "f"(b.y), "f"(b.z), "f"(b.w) : "memory");
}

// ---------------- stream/event pool: LAZY init on first kernel_launch call ----------------
// (No static-constructor CUDA calls: creating a CUDA context at library-load
//  time is the prime suspect for the R4 container failure. First call is the
//  harness's correctness run, which precedes graph capture.)
static cudaStream_t s1 = 0, s2 = 0, s3 = 0;
static cudaEvent_t eRoot = 0, eZ1 = 0, eZ = 0, eG0 = 0, eG1 = 0, eI = 0, eF0 = 0;
static int g_init_state = 0;  // 0 = untried, 1 = ok, -1 = failed (use serial fallback)

static void ensure_init() {
    if (g_init_state != 0) return;
    bool ok = true;
    ok &= (cudaStreamCreateWithFlags(&s1, cudaStreamNonBlocking) == cudaSuccess);
    ok &= (cudaStreamCreateWithFlags(&s2, cudaStreamNonBlocking) == cudaSuccess);
    ok &= (cudaStreamCreateWithFlags(&s3, cudaStreamNonBlocking) == cudaSuccess);
    ok &= (cudaEventCreateWithFlags(&eRoot, cudaEventDisableTiming) == cudaSuccess);
    ok &= (cudaEventCreateWithFlags(&eZ1, cudaEventDisableTiming) == cudaSuccess);
    ok &= (cudaEventCreateWithFlags(&eZ, cudaEventDisableTiming) == cudaSuccess);
    ok &= (cudaEventCreateWithFlags(&eG0, cudaEventDisableTiming) == cudaSuccess);
    ok &= (cudaEventCreateWithFlags(&eG1, cudaEventDisableTiming) == cudaSuccess);
    ok &= (cudaEventCreateWithFlags(&eI, cudaEventDisableTiming) == cudaSuccess);
    ok &= (cudaEventCreateWithFlags(&eF0, cudaEventDisableTiming) == cudaSuccess);
    g_init_state = ok ? 1 : -1;
}

// ---------------- launch ----------------
extern "C" void kernel_launch(void* const* d_in, const int* in_sizes, int n_in,
                              void* d_out, int out_size) {
    ensure_init();

    const float* x0   = (const float*)d_in[0];
    const float* x1   = (const float*)d_in[1];
    const float* x2   = (const float*)d_in[2];
    const float* x3   = (const float*)d_in[3];
    const float* x4   = (const float*)d_in[4];
    const int*   adj0 = (const int*)d_in[5];
    const float* adj0v= (const float*)d_in[6];
    const int*   adj1 = (const int*)d_in[7];
    const float* adj1v= (const float*)d_in[8];
    const int*   inc  = (const int*)d_in[9];
    const float* incv = (const float*)d_in[10];
    const float* cci0 = (const float*)d_in[11];
    const float* cci1 = (const float*)d_in[12];
    const float* Whbs0= (const float*)d_in[13];
    const float* ahbs0= (const float*)d_in[14];
    const float* Whbs1= (const float*)d_in[15];
    const float* ahbs1= (const float*)d_in[16];
    const float* Ws   = (const float*)d_in[17];
    const float* Wt   = (const float*)d_in[18];
    const float* Wag0 = (const float*)d_in[19];
    const float* Wag1 = (const float*)d_in[20];
    float* out = (float*)d_out;

    float *pm0, *pm1, *pms, *pmt, *pA0, *pB0, *pA1, *pB1;
    cudaGetSymbolAddress((void**)&pm0, g_m0);
    cudaGetSymbolAddress((void**)&pm1, g_m1);
    cudaGetSymbolAddress((void**)&pms, g_ms);
    cudaGetSymbolAddress((void**)&pmt, g_mt);
    cudaGetSymbolAddress((void**)&pA0, g_accA0);
    cudaGetSymbolAddress((void**)&pB0, g_accB0);
    cudaGetSymbolAddress((void**)&pA1, g_accA1);
    cudaGetSymbolAddress((void**)&pB1, g_accB1);

    if (g_init_state == 1) {
        // ======== multi-stream overlapped schedule ========
        // fork: pull side streams into the capture DAG
        cudaEventRecord(eRoot, 0);
        cudaStreamWaitEvent(s1, eRoot, 0);
        cudaStreamWaitEvent(s2, eRoot, 0);
        cudaStreamWaitEvent(s3, eRoot, 0);

        // s2: zero accumulators.  A1/B1 first so the big scatter starts ASAP.
        cudaMemsetAsync(pA1, 0, sizeof(float) * (size_t)CN1 * DD, s2);
        cudaMemsetAsync(pB1, 0, sizeof(float) * (size_t)CN1 * DD, s2);
        cudaEventRecord(eZ1, s2);
        cudaMemsetAsync(pA0, 0, sizeof(float) * (size_t)CN0 * DD, s2);
        cudaMemsetAsync(pB0, 0, sizeof(float) * (size_t)CN0 * DD, s2);
        cudaEventRecord(eZ, s2);

        // s1: chain0 — gemm(x0)
        gemm64_dual<<<(CN0 + 127) / 128, 256, 0, s1>>>(x0, Whbs0, Wt, pm0, pmt, CN0);
        cudaEventRecord(eG0, s1);

        // main: chain1 — gemm(x1)
        gemm64_dual<<<(CN1 + 127) / 128, 256, 0, 0>>>(x1, Whbs1, Ws, pm1, pms, CN1);
        cudaEventRecord(eG1, 0);

        // s3: pass-through copies, then scatter_inc (needs both gemms + zeros)
        cudaMemcpyAsync(out + (long)(CN0 + CN1) * DD, x2, sizeof(float) * (size_t)CN2 * DD,
                        cudaMemcpyDeviceToDevice, s3);
        cudaMemcpyAsync(out + (long)(CN0 + CN1 + CN2) * DD, x3, sizeof(float) * (size_t)CN3 * DD,
                        cudaMemcpyDeviceToDevice, s3);
        cudaMemcpyAsync(out + (long)(CN0 + CN1 + CN2 + CN3) * DD, x4,
                        sizeof(float) * (size_t)CN4 * DD, cudaMemcpyDeviceToDevice, s3);
        cudaStreamWaitEvent(s3, eG0, 0);
        cudaStreamWaitEvent(s3, eG1, 0);
        cudaStreamWaitEvent(s3, eZ, 0);   // eZ is recorded after ALL four memsets
        scatter_inc<<<(CNNZ * 16 + 255) / 256, 256, 0, s3>>>(pms, pmt, inc, inc + CNNZ, incv,
                                                             pB0, pB1, CNNZ);
        cudaEventRecord(eI, s3);

        // s1: scatter0 then fused0
        cudaStreamWaitEvent(s1, eZ, 0);
        scatter_edges<<<(CE0 * 16 + 255) / 256, 256, 0, s1>>>(pm0, adj0v, cci0, ahbs0,
                                                              adj0, adj0 + CE0, pA0, CE0);
        cudaStreamWaitEvent(s1, eI, 0);
        gemm64_fused<<<(CN0 + 127) / 128, 256, 0, s1>>>(pA0, pB0, Wag0, out, CN0);
        cudaEventRecord(eF0, s1);

        // main: scatter1 then fused1, then join
        cudaStreamWaitEvent(0, eZ1, 0);
        scatter_edges<<<(CE1 * 16 + 255) / 256, 256, 0, 0>>>(pm1, adj1v, cci1, ahbs1,
                                                             adj1, adj1 + CE1, pA1, CE1);
        cudaStreamWaitEvent(0, eI, 0);
        gemm64_fused<<<(CN1 + 127) / 128, 256, 0, 0>>>(pA1, pB1, Wag1,
                                                       out + (long)CN0 * DD, CN1);
        cudaStreamWaitEvent(0, eF0, 0);  // joins s1 (s2/s3 ordered via eZ/eZ1/eI)
    } else {
        // ======== serial fallback (known-good R3 schedule) ========
        cudaMemsetAsync(pA0, 0, sizeof(float) * (size_t)CN0 * DD);
        cudaMemsetAsync(pB0, 0, sizeof(float) * (size_t)CN0 * DD);
        cudaMemsetAsync(pA1, 0, sizeof(float) * (size_t)CN1 * DD);
        cudaMemsetAsync(pB1, 0, sizeof(float) * (size_t)CN1 * DD);
        gemm64_dual<<<(CN0 + 127) / 128, 256>>>(x0, Whbs0, Wt, pm0, pmt, CN0);
        gemm64_dual<<<(CN1 + 127) / 128, 256>>>(x1, Whbs1, Ws, pm1, pms, CN1);
        scatter_edges<<<(CE0 * 16 + 255) / 256, 256>>>(pm0, adj0v, cci0, ahbs0,
                                                       adj0, adj0 + CE0, pA0, CE0);
        scatter_edges<<<(CE1 * 16 + 255) / 256, 256>>>(pm1, adj1v, cci1, ahbs1,
                                                       adj1, adj1 + CE1, pA1, CE1);
        scatter_inc<<<(CNNZ * 16 + 255) / 256, 256>>>(pms, pmt, inc, inc + CNNZ, incv,
                                                      pB0, pB1, CNNZ);
        gemm64_fused<<<(CN0 + 127) / 128, 256>>>(pA0, pB0, Wag0, out, CN0);
        gemm64_fused<<<(CN1 + 127) / 128, 256>>>(pA1, pB1, Wag1, out + (long)CN0 * DD, CN1);
        cudaMemcpyAsync(out + (long)(CN0 + CN1) * DD, x2, sizeof(float) * (size_t)CN2 * DD,
                        cudaMemcpyDeviceToDevice);
        cudaMemcpyAsync(out + (long)(CN0 + CN1 + CN2) * DD, x3, sizeof(float) * (size_t)CN3 * DD,
                        cudaMemcpyDeviceToDevice);
        cudaMemcpyAsync(out + (long)(CN0 + CN1 + CN2 + CN3) * DD, x4,
                        sizeof(float) * (size_t)CN4 * DD, cudaMemcpyDeviceToDevice);
    }
}